// round 1
// baseline (speedup 1.0000x reference)
#include <cuda_runtime.h>

// BidirectionalLSTMComplex: S=1024, B=2048, H=32, IN=1, OUT=1
// Weight-stationary register kernel: 128 CTAs x 128 threads, 16 batch/CTA.
// Thread j owns row j of all six 128x32 weight matrices in registers (packed
// f32x2), reused for all 16 batch elements over all 1024 steps.

#define S_LEN 1024
#define B_TOT 2048
#define HID   32
#define GATES 128   // 4*HID
#define NB    16    // batch elements per CTA
#define NCTA  (B_TOT / NB)   // 128

typedef unsigned long long u64;

__device__ __forceinline__ void fma2(u64 &acc, u64 a, u64 b) {
    asm("fma.rn.f32x2 %0, %1, %2, %3;" : "=l"(acc) : "l"(a), "l"(b), "l"(acc));
}
__device__ __forceinline__ float hsum2(u64 v) {
    float lo, hi;
    asm("mov.b64 {%0,%1}, %2;" : "=f"(lo), "=f"(hi) : "l"(v));
    return lo + hi;
}
__device__ __forceinline__ float sigm(float x) {
    // full-precision-ish fast sigmoid: EX2 + RCP, ~2ulp
    return __fdividef(1.0f, 1.0f + __expf(-x));
}
__device__ __forceinline__ float tanh_fast(float x) {
    return 2.0f * sigm(2.0f * x) - 1.0f;
}

// load one 32-float row (128B) of a weight matrix into 16 packed u64 regs
__device__ __forceinline__ void load_row(u64 *w, const float *base) {
    const ulonglong2 *p = (const ulonglong2 *)base;
#pragma unroll
    for (int i = 0; i < 8; i++) {
        ulonglong2 q = p[i];
        w[2 * i]     = q.x;
        w[2 * i + 1] = q.y;
    }
}

__global__ void __launch_bounds__(128, 1)
lstm_kernel(const float *__restrict__ x,
            const float *__restrict__ Wih_f0, const float *__restrict__ Whh_f0, const float *__restrict__ b_f0,
            const float *__restrict__ Wih_f1, const float *__restrict__ Whh_f1, const float *__restrict__ b_f1,
            const float *__restrict__ Wih_b0, const float *__restrict__ Whh_b0, const float *__restrict__ b_b0,
            const float *__restrict__ Wih_b1, const float *__restrict__ Whh_b1, const float *__restrict__ b_b1,
            const float *__restrict__ Wlin,   const float *__restrict__ blin,
            const int *__restrict__ future_p,
            float *__restrict__ out)
{
    const int j   = threadIdx.x;          // gate row 0..127
    const int nb0 = blockIdx.x * NB;      // global batch base

    __shared__ __align__(16) float hf0s[NB][HID];
    __shared__ __align__(16) float hf1s[NB][HID];
    __shared__ __align__(16) float hb0s[NB][HID];
    __shared__ __align__(16) float hb1s[NB][HID];
    __shared__ float cf0s[NB][HID], cf1s[NB][HID], cb0s[NB][HID], cb1s[NB][HID];
    __shared__ float ga[NB][GATES];       // gate scratch A (f0 / f1)
    __shared__ float gb[NB][GATES];       // gate scratch B (b0 / b1)
    __shared__ float xs[NB], xbs[NB];
    __shared__ float wls[2 * HID];
    __shared__ float blin_s;
    __shared__ int   future_s;

    // ---- weight rows into registers (packed f32x2) ----
    u64 w_f0hh[16], w_f1ih[16], w_f1hh[16], w_b0hh[16], w_b1ih[16], w_b1hh[16];
    load_row(w_f0hh, Whh_f0 + j * HID);
    load_row(w_f1ih, Wih_f1 + j * HID);
    load_row(w_f1hh, Whh_f1 + j * HID);
    load_row(w_b0hh, Whh_b0 + j * HID);
    load_row(w_b1ih, Wih_b1 + j * HID);
    load_row(w_b1hh, Whh_b1 + j * HID);

    const float bias_f0 = b_f0[j], bias_f1 = b_f1[j];
    const float bias_b0 = b_b0[j], bias_b1 = b_b1[j];
    const float wx_f0 = Wih_f0[j];   // (128,1)
    const float wx_b0 = Wih_b0[j];

    // ---- zero-init states ----
    for (int i = j; i < NB * HID; i += 128) {
        ((float *)hf0s)[i] = 0.f; ((float *)hf1s)[i] = 0.f;
        ((float *)hb0s)[i] = 0.f; ((float *)hb1s)[i] = 0.f;
        ((float *)cf0s)[i] = 0.f; ((float *)cf1s)[i] = 0.f;
        ((float *)cb0s)[i] = 0.f; ((float *)cb1s)[i] = 0.f;
    }
    if (j < 2 * HID) wls[j] = Wlin[j];
    if (j == 0) { blin_s = blin[0]; future_s = future_p[0]; }
    __syncthreads();
    const int fut = future_s;

    const int m    = j & 31;   // hidden unit for finalize role
    const int wgrp = j >> 5;   // warp id -> batch subset for finalize

    for (int t = 0; t < S_LEN; t++) {
        // stage this step's x and x_backward
        if (j < NB) xs[j] = x[t * B_TOT + nb0 + j];
        if (j >= 64 && j < 64 + NB) {
            int tb = (fut - t) % S_LEN;
            if (tb < 0) tb += S_LEN;
            xbs[j - 64] = x[tb * B_TOT + nb0 + (j - 64)];
        }
        __syncthreads();

        // ---- Phase A: gates for f0 (x, hf0_prev) and b0 (xb, hb0_prev) ----
#pragma unroll 2
        for (int n = 0; n < NB; n++) {
            u64 a0 = 0, a1 = 0, d0 = 0, d1 = 0;
            const ulonglong2 *hf = (const ulonglong2 *)hf0s[n];
            const ulonglong2 *hb = (const ulonglong2 *)hb0s[n];
#pragma unroll
            for (int c = 0; c < 8; c++) {
                ulonglong2 u = hf[c];
                fma2(a0, w_f0hh[2 * c],     u.x);
                fma2(a1, w_f0hh[2 * c + 1], u.y);
                ulonglong2 v = hb[c];
                fma2(d0, w_b0hh[2 * c],     v.x);
                fma2(d1, w_b0hh[2 * c + 1], v.y);
            }
            ga[n][j] = hsum2(a0) + hsum2(a1) + bias_f0 + wx_f0 * xs[n];
            gb[n][j] = hsum2(d0) + hsum2(d1) + bias_b0 + wx_b0 * xbs[n];
        }
        __syncthreads();

        // ---- Finalize f0 and b0 ----
#pragma unroll
        for (int u = 0; u < 4; u++) {
            int n = wgrp * 4 + u;
            {
                float gi = ga[n][m], gf = ga[n][m + 32], gg = ga[n][m + 64], go = ga[n][m + 96];
                float c2 = sigm(gf) * cf0s[n][m] + sigm(gi) * tanh_fast(gg);
                cf0s[n][m] = c2;
                hf0s[n][m] = sigm(go) * tanh_fast(c2);
            }
            {
                float gi = gb[n][m], gf = gb[n][m + 32], gg = gb[n][m + 64], go = gb[n][m + 96];
                float c2 = sigm(gf) * cb0s[n][m] + sigm(gi) * tanh_fast(gg);
                cb0s[n][m] = c2;
                hb0s[n][m] = sigm(go) * tanh_fast(c2);
            }
        }
        __syncthreads();

        // ---- Phase B: gates for f1 = Wih_f1*hf0_new + Whh_f1*hf1_old ----
#pragma unroll 2
        for (int n = 0; n < NB; n++) {
            u64 a0 = 0, a1 = 0, a2 = 0, a3 = 0;
            const ulonglong2 *hu = (const ulonglong2 *)hf0s[n];
            const ulonglong2 *hh = (const ulonglong2 *)hf1s[n];
#pragma unroll
            for (int c = 0; c < 8; c++) {
                ulonglong2 u = hu[c];
                fma2(a0, w_f1ih[2 * c],     u.x);
                fma2(a1, w_f1ih[2 * c + 1], u.y);
                ulonglong2 v = hh[c];
                fma2(a2, w_f1hh[2 * c],     v.x);
                fma2(a3, w_f1hh[2 * c + 1], v.y);
            }
            ga[n][j] = hsum2(a0) + hsum2(a1) + hsum2(a2) + hsum2(a3) + bias_f1;
        }
        __syncthreads();

        // ---- Finalize f1 ----
#pragma unroll
        for (int u = 0; u < 4; u++) {
            int n = wgrp * 4 + u;
            float gi = ga[n][m], gf = ga[n][m + 32], gg = ga[n][m + 64], go = ga[n][m + 96];
            float c2 = sigm(gf) * cf1s[n][m] + sigm(gi) * tanh_fast(gg);
            cf1s[n][m] = c2;
            hf1s[n][m] = sigm(go) * tanh_fast(c2);
        }
        __syncthreads();

        // ---- Phase C: gates for b1 = Wih_b1*hb0_new + Whh_b1*hf1_NEW ----
        // (reference replicates a bug: b1's h-state is the new hf1)
#pragma unroll 2
        for (int n = 0; n < NB; n++) {
            u64 a0 = 0, a1 = 0, a2 = 0, a3 = 0;
            const ulonglong2 *hu = (const ulonglong2 *)hb0s[n];
            const ulonglong2 *hh = (const ulonglong2 *)hf1s[n];
#pragma unroll
            for (int c = 0; c < 8; c++) {
                ulonglong2 u = hu[c];
                fma2(a0, w_b1ih[2 * c],     u.x);
                fma2(a1, w_b1ih[2 * c + 1], u.y);
                ulonglong2 v = hh[c];
                fma2(a2, w_b1hh[2 * c],     v.x);
                fma2(a3, w_b1hh[2 * c + 1], v.y);
            }
            gb[n][j] = hsum2(a0) + hsum2(a1) + hsum2(a2) + hsum2(a3) + bias_b1;
        }
        __syncthreads();

        // ---- Finalize b1 ----
#pragma unroll
        for (int u = 0; u < 4; u++) {
            int n = wgrp * 4 + u;
            float gi = gb[n][m], gf = gb[n][m + 32], gg = gb[n][m + 64], go = gb[n][m + 96];
            float c2 = sigm(gf) * cb1s[n][m] + sigm(gi) * tanh_fast(gg);
            cb1s[n][m] = c2;
            hb1s[n][m] = sigm(go) * tanh_fast(c2);
        }
        __syncthreads();

        // ---- Output: out[n][t] = [hf1, hb1] . Wlin + blin ----
        if (j < NB) {
            int n = j;
            float acc = blin_s;
#pragma unroll
            for (int k = 0; k < HID; k++) acc += wls[k] * hf1s[n][k];
#pragma unroll
            for (int k = 0; k < HID; k++) acc += wls[HID + k] * hb1s[n][k];
            out[(nb0 + n) * S_LEN + t] = acc;
        }
        // next-iteration xs writers are the same threads that did the output;
        // the top-of-loop __syncthreads orders everything else.
    }
}

extern "C" void kernel_launch(void *const *d_in, const int *in_sizes, int n_in,
                              void *d_out, int out_size)
{
    const float *x      = (const float *)d_in[0];
    const float *Wih_f0 = (const float *)d_in[1];
    const float *Whh_f0 = (const float *)d_in[2];
    const float *b_f0   = (const float *)d_in[3];
    const float *Wih_f1 = (const float *)d_in[4];
    const float *Whh_f1 = (const float *)d_in[5];
    const float *b_f1   = (const float *)d_in[6];
    const float *Wih_b0 = (const float *)d_in[7];
    const float *Whh_b0 = (const float *)d_in[8];
    const float *b_b0   = (const float *)d_in[9];
    const float *Wih_b1 = (const float *)d_in[10];
    const float *Whh_b1 = (const float *)d_in[11];
    const float *b_b1   = (const float *)d_in[12];
    const float *Wlin   = (const float *)d_in[13];
    const float *blin   = (const float *)d_in[14];
    const int   *future = (const int *)d_in[15];
    float *out = (float *)d_out;

    lstm_kernel<<<NCTA, 128>>>(x,
                               Wih_f0, Whh_f0, b_f0,
                               Wih_f1, Whh_f1, b_f1,
                               Wih_b0, Whh_b0, b_b0,
                               Wih_b1, Whh_b1, b_b1,
                               Wlin, blin, future, out);
}

// round 2
// speedup vs baseline: 2.4340x; 2.4340x over previous
#include <cuda_runtime.h>

// BidirectionalLSTMComplex: S=1024, B=2048, H=32, IN=1, OUT=1
// Round 2: fwd/bwd-split 256-thread CTAs, software-pipelined (f0 one step
// ahead), 2 CTAs/SM target (128 regs), tanh.approx activations.

#define S_LEN 1024
#define B_TOT 2048
#define HID   32
#define GATES 128
#define NB    8
#define NCTA  (B_TOT / NB)   // 256
#define HP    36             // padded h-row (conflict-free out-dot, 16B aligned)

typedef unsigned long long u64;

__device__ __forceinline__ void fma2(u64 &acc, u64 a, u64 b) {
    asm("fma.rn.f32x2 %0, %1, %2, %3;" : "=l"(acc) : "l"(a), "l"(b), "l"(acc));
}
__device__ __forceinline__ void add2(u64 &a, u64 b) {
    asm("add.rn.f32x2 %0, %1, %2;" : "=l"(a) : "l"(a), "l"(b));
}
__device__ __forceinline__ float hsum2(u64 v) {
    float lo, hi;
    asm("mov.b64 {%0,%1}, %2;" : "=f"(lo), "=f"(hi) : "l"(v));
    return lo + hi;
}
__device__ __forceinline__ float tanh_fast(float x) {
    float y;
    asm("tanh.approx.f32 %0, %1;" : "=f"(y) : "f"(x));
    return y;
}
__device__ __forceinline__ float sigm(float x) {
    return fmaf(tanh_fast(x * 0.5f), 0.5f, 0.5f);
}

// load one 32-float row (128B) into 16 packed u64 regs
__device__ __forceinline__ void load_row(u64 *w, const float *base) {
    const ulonglong2 *p = (const ulonglong2 *)base;
#pragma unroll
    for (int i = 0; i < 8; i++) {
        ulonglong2 q = p[i];
        w[2 * i]     = q.x;
        w[2 * i + 1] = q.y;
    }
}

// one LSTM unit update: g points at ga[n], c at cs[n], h at hs[n] (padded row)
__device__ __forceinline__ void cell_finalize(const float *g, float *c, float *h, int m) {
    float gi = g[m], gf = g[m + 32], gg = g[m + 64], go = g[m + 96];
    float c2 = sigm(gf) * c[m] + sigm(gi) * tanh_fast(gg);
    c[m] = c2;
    h[m] = sigm(go) * tanh_fast(c2);
}

__global__ void __launch_bounds__(256, 2)
lstm_kernel(const float *__restrict__ x,
            const float *__restrict__ Wih_f0, const float *__restrict__ Whh_f0, const float *__restrict__ b_f0,
            const float *__restrict__ Wih_f1, const float *__restrict__ Whh_f1, const float *__restrict__ b_f1,
            const float *__restrict__ Wih_b0, const float *__restrict__ Whh_b0, const float *__restrict__ b_b0,
            const float *__restrict__ Wih_b1, const float *__restrict__ Whh_b1, const float *__restrict__ b_b1,
            const float *__restrict__ Wlin,   const float *__restrict__ blin,
            const int *__restrict__ future_p,
            float *__restrict__ out)
{
    const int tid  = threadIdx.x;
    const int j    = tid & 127;      // gate row within the half
    const bool isF = tid < 128;
    const int nb0  = blockIdx.x * NB;

    __shared__ __align__(16) float hf0s[NB][HP];
    __shared__ __align__(16) float hf1s[NB][HP];
    __shared__ __align__(16) float hb0s[NB][HP];
    __shared__ __align__(16) float hb1s[NB][HP];
    __shared__ float cf0s[NB][HID], cf1s[NB][HID], cb0s[NB][HID], cb1s[NB][HID];
    __shared__ float gaF[NB][GATES];   // forward-half gate scratch
    __shared__ float gaB[NB][GATES];   // backward-half gate scratch
    __shared__ float xs[NB], xbs[NB];
    __shared__ float wls[2 * HID];
    __shared__ float blin_s;

    // ---- per-half weight rows into registers ----
    u64 w0[16], w1[16], w2[16];
    float bias0, bias1, wx;
    if (isF) {
        load_row(w0, Whh_f0 + j * HID);   // layer0 fwd recurrent
        load_row(w1, Wih_f1 + j * HID);   // layer1 fwd input
        load_row(w2, Whh_f1 + j * HID);   // layer1 fwd recurrent (on hf1)
        bias0 = b_f0[j]; bias1 = b_f1[j]; wx = Wih_f0[j];
    } else {
        load_row(w0, Whh_b0 + j * HID);   // layer0 bwd recurrent
        load_row(w1, Wih_b1 + j * HID);   // layer1 bwd input (on hb0)
        load_row(w2, Whh_b1 + j * HID);   // layer1 bwd recurrent (on hf1 -- replicated bug)
        bias0 = b_b0[j]; bias1 = b_b1[j]; wx = Wih_b0[j];
    }
    const int fut = future_p[0];

    // ---- zero-init states ----
    for (int i = tid; i < NB * HP; i += 256) {
        ((float *)hf0s)[i] = 0.f; ((float *)hf1s)[i] = 0.f;
        ((float *)hb0s)[i] = 0.f; ((float *)hb1s)[i] = 0.f;
    }
    for (int i = tid; i < NB * HID; i += 256) {
        ((float *)cf0s)[i] = 0.f; ((float *)cf1s)[i] = 0.f;
        ((float *)cb0s)[i] = 0.f; ((float *)cb1s)[i] = 0.f;
    }
    if (tid < 2 * HID) wls[tid] = Wlin[tid];
    if (tid == 0) blin_s = blin[0];

    // stage x_0 and xb_0
    if (tid < NB) {
        xs[tid] = x[nb0 + tid];
    } else if (tid < 2 * NB) {
        int r = fut % S_LEN; if (r < 0) r += S_LEN;
        xbs[tid - NB] = x[r * B_TOT + nb0 + (tid - NB)];
    }
    __syncthreads();

    const int m  = j & 31;    // unit index for finalize
    const int ng = j >> 5;    // warp id within half -> batch group

    // ---- prologue: f0_0 (h,c are zero -> gates are just bias + wx*x) ----
    if (isF) {
#pragma unroll
        for (int n = 0; n < NB; n++) gaF[n][j] = bias0 + wx * xs[n];
    }
    __syncthreads();
    if (isF) {
        cell_finalize(gaF[ng],     cf0s[ng],     hf0s[ng],     m);
        cell_finalize(gaF[ng + 4], cf0s[ng + 4], hf0s[ng + 4], m);
    }
    __syncthreads();

    for (int t = 0; t < S_LEN; t++) {
        // ==== Phase 1 compute:  F: f1_t gates     Bk: b0_t gates ====
        if (isF) {
#pragma unroll 2
            for (int n = 0; n < NB; n++) {
                u64 a0 = 0, a1 = 0, a2 = 0, a3 = 0;
                const ulonglong2 *hu = (const ulonglong2 *)hf0s[n];
                const ulonglong2 *hh = (const ulonglong2 *)hf1s[n];
#pragma unroll
                for (int c = 0; c < 8; c++) {
                    ulonglong2 u = hu[c];
                    fma2(a0, w1[2 * c],     u.x);
                    fma2(a1, w1[2 * c + 1], u.y);
                    ulonglong2 v = hh[c];
                    fma2(a2, w2[2 * c],     v.x);
                    fma2(a3, w2[2 * c + 1], v.y);
                }
                add2(a0, a1); add2(a2, a3); add2(a0, a2);
                gaF[n][j] = hsum2(a0) + bias1;
            }
        } else {
#pragma unroll 2
            for (int n = 0; n < NB; n++) {
                u64 a0 = 0, a1 = 0;
                const ulonglong2 *hb = (const ulonglong2 *)hb0s[n];
#pragma unroll
                for (int c = 0; c < 8; c++) {
                    ulonglong2 u = hb[c];
                    fma2(a0, w0[2 * c],     u.x);
                    fma2(a1, w0[2 * c + 1], u.y);
                }
                add2(a0, a1);
                gaB[n][j] = hsum2(a0) + bias0 + wx * xbs[n];
            }
        }
        __syncthreads();

        // ==== Phase 1 finalize:  F: hf1_t,cf1_t   Bk: hb0_t,cb0_t  + stage x ====
        if (isF) {
            cell_finalize(gaF[ng],     cf1s[ng],     hf1s[ng],     m);
            cell_finalize(gaF[ng + 4], cf1s[ng + 4], hf1s[ng + 4], m);
            if (j < NB) {
                if (t + 1 < S_LEN) xs[j] = x[(t + 1) * B_TOT + nb0 + j];
            } else if (j < 2 * NB) {
                int r = (fut - (t + 1)) % S_LEN; if (r < 0) r += S_LEN;
                xbs[j - NB] = x[r * B_TOT + nb0 + (j - NB)];
            }
        } else {
            cell_finalize(gaB[ng],     cb0s[ng],     hb0s[ng],     m);
            cell_finalize(gaB[ng + 4], cb0s[ng + 4], hb0s[ng + 4], m);
        }
        __syncthreads();

        // ==== Phase 2 compute:  F: f0_{t+1} gates   Bk: b1_t gates ====
        if (isF) {
#pragma unroll 2
            for (int n = 0; n < NB; n++) {
                u64 a0 = 0, a1 = 0;
                const ulonglong2 *hu = (const ulonglong2 *)hf0s[n];
#pragma unroll
                for (int c = 0; c < 8; c++) {
                    ulonglong2 u = hu[c];
                    fma2(a0, w0[2 * c],     u.x);
                    fma2(a1, w0[2 * c + 1], u.y);
                }
                add2(a0, a1);
                gaF[n][j] = hsum2(a0) + bias0 + wx * xs[n];
            }
        } else {
#pragma unroll 2
            for (int n = 0; n < NB; n++) {
                u64 a0 = 0, a1 = 0, a2 = 0, a3 = 0;
                const ulonglong2 *hu = (const ulonglong2 *)hb0s[n];
                const ulonglong2 *hh = (const ulonglong2 *)hf1s[n];   // replicated bug: uses hf1
#pragma unroll
                for (int c = 0; c < 8; c++) {
                    ulonglong2 u = hu[c];
                    fma2(a0, w1[2 * c],     u.x);
                    fma2(a1, w1[2 * c + 1], u.y);
                    ulonglong2 v = hh[c];
                    fma2(a2, w2[2 * c],     v.x);
                    fma2(a3, w2[2 * c + 1], v.y);
                }
                add2(a0, a1); add2(a2, a3); add2(a0, a2);
                gaB[n][j] = hsum2(a0) + bias1;
            }
        }
        __syncthreads();

        // ==== Phase 2 finalize:  F: hf0_{t+1},cf0   Bk: hb1_t,cb1_t ====
        if (isF) {
            cell_finalize(gaF[ng],     cf0s[ng],     hf0s[ng],     m);
            cell_finalize(gaF[ng + 4], cf0s[ng + 4], hf0s[ng + 4], m);
        } else {
            cell_finalize(gaB[ng],     cb1s[ng],     hb1s[ng],     m);
            cell_finalize(gaB[ng + 4], cb1s[ng + 4], hb1s[ng + 4], m);
        }
        __syncthreads();

        // ==== output_t: Bk threads j<NB (light phase-1 next iter) ====
        // Reads hf1_t (P1fin, synced) and hb1_t (P2fin, synced). The next
        // write to these arrays is P1fin(t+1), which is after the next
        // barrier, so racing with P1comp(t+1) is safe (reads only).
        if (!isF && j < NB) {
            int n = j;
            float acc = blin_s;
#pragma unroll
            for (int k = 0; k < HID; k++) acc += wls[k] * hf1s[n][k];
#pragma unroll
            for (int k = 0; k < HID; k++) acc += wls[HID + k] * hb1s[n][k];
            out[(nb0 + n) * S_LEN + t] = acc;
        }
    }
}

extern "C" void kernel_launch(void *const *d_in, const int *in_sizes, int n_in,
                              void *d_out, int out_size)
{
    const float *x      = (const float *)d_in[0];
    const float *Wih_f0 = (const float *)d_in[1];
    const float *Whh_f0 = (const float *)d_in[2];
    const float *b_f0   = (const float *)d_in[3];
    const float *Wih_f1 = (const float *)d_in[4];
    const float *Whh_f1 = (const float *)d_in[5];
    const float *b_f1   = (const float *)d_in[6];
    const float *Wih_b0 = (const float *)d_in[7];
    const float *Whh_b0 = (const float *)d_in[8];
    const float *b_b0   = (const float *)d_in[9];
    const float *Wih_b1 = (const float *)d_in[10];
    const float *Whh_b1 = (const float *)d_in[11];
    const float *b_b1   = (const float *)d_in[12];
    const float *Wlin   = (const float *)d_in[13];
    const float *blin   = (const float *)d_in[14];
    const int   *future = (const int *)d_in[15];
    float *out = (float *)d_out;

    lstm_kernel<<<NCTA, 256>>>(x,
                               Wih_f0, Whh_f0, b_f0,
                               Wih_f1, Whh_f1, b_f1,
                               Wih_b0, Whh_b0, b_b0,
                               Wih_b1, Whh_b1, b_b1,
                               Wlin, blin, future, out);
}

// round 3
// speedup vs baseline: 3.2084x; 1.3182x over previous
#include <cuda_runtime.h>

// BidirectionalLSTMComplex: S=1024, B=2048, H=32, IN=1, OUT=1
// Round 3: single fused compute phase per step (f0_{t+1}+f1_t share hf0_t load;
// b0_t+b1_{t-1} share hb0/hf1 loads), 2 barriers/step, LDS:FMA = 1:3.

#define S_LEN 1024
#define B_TOT 2048
#define HID   32
#define GATES 128
#define NB    8
#define NCTA  (B_TOT / NB)   // 256
#define HP    36             // padded h row: 144B, 16B-aligned

typedef unsigned long long u64;

__device__ __forceinline__ void fma2(u64 &acc, u64 a, u64 b) {
    asm("fma.rn.f32x2 %0, %1, %2, %3;" : "=l"(acc) : "l"(a), "l"(b), "l"(acc));
}
__device__ __forceinline__ void add2(u64 &a, u64 b) {
    asm("add.rn.f32x2 %0, %1, %2;" : "=l"(a) : "l"(a), "l"(b));
}
__device__ __forceinline__ float hsum2(u64 v) {
    float lo, hi;
    asm("mov.b64 {%0,%1}, %2;" : "=f"(lo), "=f"(hi) : "l"(v));
    return lo + hi;
}
__device__ __forceinline__ float tanh_fast(float x) {
    float y;
    asm("tanh.approx.f32 %0, %1;" : "=f"(y) : "f"(x));
    return y;
}
__device__ __forceinline__ float sigm(float x) {
    return fmaf(tanh_fast(x * 0.5f), 0.5f, 0.5f);
}

__device__ __forceinline__ void load_row(u64 *w, const float *base) {
    const ulonglong2 *p = (const ulonglong2 *)base;
#pragma unroll
    for (int i = 0; i < 8; i++) {
        ulonglong2 q = p[i];
        w[2 * i]     = q.x;
        w[2 * i + 1] = q.y;
    }
}

__device__ __forceinline__ void cell_finalize(const float *g, float *c, float *h, int m) {
    float gi = g[m], gf = g[m + 32], gg = g[m + 64], go = g[m + 96];
    float c2 = sigm(gf) * c[m] + sigm(gi) * tanh_fast(gg);
    c[m] = c2;
    h[m] = sigm(go) * tanh_fast(c2);
}

__global__ void __launch_bounds__(256, 2)
lstm_kernel(const float *__restrict__ x,
            const float *__restrict__ Wih_f0, const float *__restrict__ Whh_f0, const float *__restrict__ b_f0,
            const float *__restrict__ Wih_f1, const float *__restrict__ Whh_f1, const float *__restrict__ b_f1,
            const float *__restrict__ Wih_b0, const float *__restrict__ Whh_b0, const float *__restrict__ b_b0,
            const float *__restrict__ Wih_b1, const float *__restrict__ Whh_b1, const float *__restrict__ b_b1,
            const float *__restrict__ Wlin,   const float *__restrict__ blin,
            const int *__restrict__ future_p,
            float *__restrict__ out)
{
    const int tid  = threadIdx.x;
    const int j    = tid & 127;
    const bool isF = tid < 128;
    const int nb0  = blockIdx.x * NB;

    __shared__ __align__(16) float hf0s[NB][HP];
    __shared__ __align__(16) float hf1s[2][NB][HP];   // parity double buffer
    __shared__ __align__(16) float hb0s[NB][HP];
    __shared__ __align__(16) float hb1s[NB][HP];
    __shared__ float cf0s[NB][HID], cf1s[NB][HID], cb0s[NB][HID], cb1s[NB][HID];
    __shared__ float gF0[NB][GATES], gF1[NB][GATES];
    __shared__ float gB0[NB][GATES], gB1[NB][GATES];
    __shared__ float xs[NB], xbs[NB];
    __shared__ __align__(16) float wls[2 * HID];
    __shared__ float blin_s;

    // per-half weight rows
    u64 w0[16], w1[16], w2[16];
    float bias0, bias1, wx;
    if (isF) {
        load_row(w0, Whh_f0 + j * HID);   // f0 recurrent
        load_row(w1, Wih_f1 + j * HID);   // f1 input  (on hf0)
        load_row(w2, Whh_f1 + j * HID);   // f1 recurrent (on hf1)
        bias0 = b_f0[j]; bias1 = b_f1[j]; wx = Wih_f0[j];
    } else {
        load_row(w0, Whh_b0 + j * HID);   // b0 recurrent
        load_row(w1, Wih_b1 + j * HID);   // b1 input  (on hb0)
        load_row(w2, Whh_b1 + j * HID);   // b1 recurrent (on hf1 -- replicated bug)
        bias0 = b_b0[j]; bias1 = b_b1[j]; wx = Wih_b0[j];
    }
    const int fut = future_p[0];

    // zero-init
    for (int i = tid; i < NB * HP; i += 256) {
        ((float *)hf0s)[i] = 0.f; ((float *)hb0s)[i] = 0.f; ((float *)hb1s)[i] = 0.f;
    }
    for (int i = tid; i < 2 * NB * HP; i += 256) ((float *)hf1s)[i] = 0.f;
    for (int i = tid; i < NB * HID; i += 256) {
        ((float *)cf0s)[i] = 0.f; ((float *)cf1s)[i] = 0.f;
        ((float *)cb0s)[i] = 0.f; ((float *)cb1s)[i] = 0.f;
    }
    if (tid < 2 * HID) wls[tid] = Wlin[tid];
    if (tid == 0) blin_s = blin[0];

    // stage x_0 (fwd) and xb_0 (bwd)
    if (tid < NB) {
        xs[tid] = x[nb0 + tid];
    } else if (tid >= 128 && tid < 128 + NB) {
        int r = fut % S_LEN; if (r < 0) r += S_LEN;
        xbs[tid - 128] = x[r * B_TOT + nb0 + (tid - 128)];
    }
    __syncthreads();

    const int m  = j & 31;
    const int ng = j >> 5;

    // ---- prologue: f0_0 from zero state ----
    if (isF) {
#pragma unroll
        for (int n = 0; n < NB; n++) gF0[n][j] = bias0 + wx * xs[n];
    }
    __syncthreads();
    if (isF) {
        cell_finalize(gF0[ng],     cf0s[ng],     hf0s[ng],     m);
        cell_finalize(gF0[ng + 4], cf0s[ng + 4], hf0s[ng + 4], m);
    }
    // restage xs = x_1 (read of x_0 happened before previous barrier)
    if (tid < NB) xs[tid] = x[B_TOT + nb0 + tid];
    __syncthreads();

    // main loop. step t computes: f0_{t+1}, f1_t, b0_t, b1_{t-1}, out_{t-2}
    for (int t = 0; t < S_LEN + 2; t++) {
        const int pb = (t + 1) & 1;   // buffer holding hf1_{t-1}
        const int cb = t & 1;         // buffer written with hf1_t (and holding hf1_{t-2} now)
        float xreg = 0.f, xbreg = 0.f;

        // ==== compute phase ====
        if (isF) {
            if (t < S_LEN) {
                if (j < NB && t + 2 < S_LEN) xreg = x[(t + 2) * B_TOT + nb0 + j];
#pragma unroll 1
                for (int n = 0; n < NB; n++) {
                    u64 a0 = 0, a1 = 0, a2 = 0, a3 = 0, a4 = 0, a5 = 0;
                    const ulonglong2 *hu = (const ulonglong2 *)hf0s[n];
                    const ulonglong2 *hv = (const ulonglong2 *)hf1s[pb][n];
#pragma unroll
                    for (int c = 0; c < 8; c++) {
                        ulonglong2 u = hu[c];
                        fma2(a0, w0[2 * c],     u.x);
                        fma2(a1, w0[2 * c + 1], u.y);
                        fma2(a2, w1[2 * c],     u.x);
                        fma2(a3, w1[2 * c + 1], u.y);
                        ulonglong2 v = hv[c];
                        fma2(a4, w2[2 * c],     v.x);
                        fma2(a5, w2[2 * c + 1], v.y);
                    }
                    add2(a0, a1);
                    gF0[n][j] = hsum2(a0) + bias0 + wx * xs[n];     // f0_{t+1} gates
                    add2(a2, a3); add2(a4, a5); add2(a2, a4);
                    gF1[n][j] = hsum2(a2) + bias1;                  // f1_t gates
                }
            }
            // output out_{t-2} on warp 3 lanes 24..31 (reads hf1_{t-2}=buf cb, hb1_{t-2})
            if (t >= 2 && j >= 120) {
                int n = j - 120;
                const ulonglong2 *pf = (const ulonglong2 *)hf1s[cb][n];
                const ulonglong2 *pk = (const ulonglong2 *)hb1s[n];
                const ulonglong2 *wf = (const ulonglong2 *)wls;
                u64 acc = 0, acc2 = 0;
#pragma unroll
                for (int c = 0; c < 8; c++) {
                    ulonglong2 u = pf[c], wu = wf[c];
                    fma2(acc,  wu.x, u.x);
                    fma2(acc2, wu.y, u.y);
                    ulonglong2 v = pk[c], wv = wf[c + 8];
                    fma2(acc,  wv.x, v.x);
                    fma2(acc2, wv.y, v.y);
                }
                add2(acc, acc2);
                out[(nb0 + n) * S_LEN + (t - 2)] = hsum2(acc) + blin_s;
            }
        } else {
            if (t <= S_LEN) {
                if (j < NB && t + 1 < S_LEN) {
                    int r = (fut - (t + 1)) % S_LEN; if (r < 0) r += S_LEN;
                    xbreg = x[r * B_TOT + nb0 + j];
                }
#pragma unroll 1
                for (int n = 0; n < NB; n++) {
                    u64 a0 = 0, a1 = 0, a2 = 0, a3 = 0, a4 = 0, a5 = 0;
                    const ulonglong2 *hu = (const ulonglong2 *)hb0s[n];
                    const ulonglong2 *hv = (const ulonglong2 *)hf1s[pb][n];
#pragma unroll
                    for (int c = 0; c < 8; c++) {
                        ulonglong2 u = hu[c];
                        fma2(a0, w0[2 * c],     u.x);
                        fma2(a1, w0[2 * c + 1], u.y);
                        fma2(a2, w1[2 * c],     u.x);
                        fma2(a3, w1[2 * c + 1], u.y);
                        ulonglong2 v = hv[c];
                        fma2(a4, w2[2 * c],     v.x);
                        fma2(a5, w2[2 * c + 1], v.y);
                    }
                    add2(a0, a1);
                    gB0[n][j] = hsum2(a0) + bias0 + wx * xbs[n];    // b0_t gates
                    add2(a2, a3); add2(a4, a5); add2(a2, a4);
                    gB1[n][j] = hsum2(a2) + bias1;                  // b1_{t-1} gates
                }
            }
        }
        __syncthreads();

        // ==== finalize phase ====
        if (isF) {
            if (t < S_LEN) {
                cell_finalize(gF0[ng],     cf0s[ng],     hf0s[ng],     m);       // f0_{t+1}
                cell_finalize(gF0[ng + 4], cf0s[ng + 4], hf0s[ng + 4], m);
                cell_finalize(gF1[ng],     cf1s[ng],     hf1s[cb][ng],     m);   // f1_t
                cell_finalize(gF1[ng + 4], cf1s[ng + 4], hf1s[cb][ng + 4], m);
                if (j < NB) xs[j] = xreg;           // x_{t+2}
            }
        } else {
            if (t < S_LEN) {
                cell_finalize(gB0[ng],     cb0s[ng],     hb0s[ng],     m);       // b0_t
                cell_finalize(gB0[ng + 4], cb0s[ng + 4], hb0s[ng + 4], m);
                if (j < NB) xbs[j] = xbreg;         // xb_{t+1}
            }
            if (t >= 1 && t <= S_LEN) {
                cell_finalize(gB1[ng],     cb1s[ng],     hb1s[ng],     m);       // b1_{t-1}
                cell_finalize(gB1[ng + 4], cb1s[ng + 4], hb1s[ng + 4], m);
            }
        }
        __syncthreads();
    }
}

extern "C" void kernel_launch(void *const *d_in, const int *in_sizes, int n_in,
                              void *d_out, int out_size)
{
    const float *x      = (const float *)d_in[0];
    const float *Wih_f0 = (const float *)d_in[1];
    const float *Whh_f0 = (const float *)d_in[2];
    const float *b_f0   = (const float *)d_in[3];
    const float *Wih_f1 = (const float *)d_in[4];
    const float *Whh_f1 = (const float *)d_in[5];
    const float *b_f1   = (const float *)d_in[6];
    const float *Wih_b0 = (const float *)d_in[7];
    const float *Whh_b0 = (const float *)d_in[8];
    const float *b_b0   = (const float *)d_in[9];
    const float *Wih_b1 = (const float *)d_in[10];
    const float *Whh_b1 = (const float *)d_in[11];
    const float *b_b1   = (const float *)d_in[12];
    const float *Wlin   = (const float *)d_in[13];
    const float *blin   = (const float *)d_in[14];
    const int   *future = (const int *)d_in[15];
    float *out = (float *)d_out;

    lstm_kernel<<<NCTA, 256>>>(x,
                               Wih_f0, Whh_f0, b_f0,
                               Wih_f1, Whh_f1, b_f1,
                               Wih_b0, Whh_b0, b_b0,
                               Wih_b1, Whh_b1, b_b1,
                               Wlin, blin, future, out);
}

// round 4
// speedup vs baseline: 3.3485x; 1.0437x over previous
#include <cuda_runtime.h>

// BidirectionalLSTMComplex: S=1024, B=2048, H=32, IN=1, OUT=1
// Round 4: per-half named barriers (comp->fin), parity buffers for hf1/hb1,
// interleaved finalize MUFU chains. One full barrier per step.

#define S_LEN 1024
#define B_TOT 2048
#define HID   32
#define GATES 128
#define NB    8
#define NCTA  (B_TOT / NB)   // 256
#define HP    36

typedef unsigned long long u64;

__device__ __forceinline__ void fma2(u64 &acc, u64 a, u64 b) {
    asm("fma.rn.f32x2 %0, %1, %2, %3;" : "=l"(acc) : "l"(a), "l"(b), "l"(acc));
}
__device__ __forceinline__ void add2(u64 &a, u64 b) {
    asm("add.rn.f32x2 %0, %1, %2;" : "=l"(a) : "l"(a), "l"(b));
}
__device__ __forceinline__ float hsum2(u64 v) {
    float lo, hi;
    asm("mov.b64 {%0,%1}, %2;" : "=f"(lo), "=f"(hi) : "l"(v));
    return lo + hi;
}
__device__ __forceinline__ float tanh_fast(float x) {
    float y;
    asm("tanh.approx.f32 %0, %1;" : "=f"(y) : "f"(x));
    return y;
}
__device__ __forceinline__ float sigm(float x) {
    return fmaf(tanh_fast(x * 0.5f), 0.5f, 0.5f);
}

__device__ __forceinline__ void load_row(u64 *w, const float *base) {
    const ulonglong2 *p = (const ulonglong2 *)base;
#pragma unroll
    for (int i = 0; i < 8; i++) {
        ulonglong2 q = p[i];
        w[2 * i]     = q.x;
        w[2 * i + 1] = q.y;
    }
}

// two independent unit updates, MUFUs interleaved to pipeline at rt8
__device__ __forceinline__ void cell2(const float *g0, float *c0, float *h0,
                                      const float *g1, float *c1, float *h1, int m) {
    float ai = g0[m], af = g0[m + 32], ag = g0[m + 64], ao = g0[m + 96];
    float bi = g1[m], bf = g1[m + 32], bg = g1[m + 64], bo = g1[m + 96];
    float sfa = sigm(af), sfb = sigm(bf);
    float sia = sigm(ai), sib = sigm(bi);
    float tga = tanh_fast(ag), tgb = tanh_fast(bg);
    float soa = sigm(ao), sob = sigm(bo);
    float c2a = sfa * c0[m] + sia * tga;
    float c2b = sfb * c1[m] + sib * tgb;
    c0[m] = c2a; c1[m] = c2b;
    h0[m] = soa * tanh_fast(c2a);
    h1[m] = sob * tanh_fast(c2b);
}

__global__ void __launch_bounds__(256, 2)
lstm_kernel(const float *__restrict__ x,
            const float *__restrict__ Wih_f0, const float *__restrict__ Whh_f0, const float *__restrict__ b_f0,
            const float *__restrict__ Wih_f1, const float *__restrict__ Whh_f1, const float *__restrict__ b_f1,
            const float *__restrict__ Wih_b0, const float *__restrict__ Whh_b0, const float *__restrict__ b_b0,
            const float *__restrict__ Wih_b1, const float *__restrict__ Whh_b1, const float *__restrict__ b_b1,
            const float *__restrict__ Wlin,   const float *__restrict__ blin,
            const int *__restrict__ future_p,
            float *__restrict__ out)
{
    const int tid  = threadIdx.x;
    const int j    = tid & 127;
    const bool isF = tid < 128;
    const int nb0  = blockIdx.x * NB;

    __shared__ __align__(16) float hf0s[NB][HP];
    __shared__ __align__(16) float hf1s[2][NB][HP];   // parity double buffer
    __shared__ __align__(16) float hb0s[NB][HP];
    __shared__ __align__(16) float hb1s[2][NB][HP];   // parity double buffer
    __shared__ float cf0s[NB][HID], cf1s[NB][HID], cb0s[NB][HID], cb1s[NB][HID];
    __shared__ float gF0[NB][GATES], gF1[NB][GATES];
    __shared__ float gB0[NB][GATES], gB1[NB][GATES];
    __shared__ float xs[NB], xbs[NB];
    __shared__ __align__(16) float wls[2 * HID];
    __shared__ float blin_s;

    u64 w0[16], w1[16], w2[16];
    float bias0, bias1, wx;
    if (isF) {
        load_row(w0, Whh_f0 + j * HID);
        load_row(w1, Wih_f1 + j * HID);
        load_row(w2, Whh_f1 + j * HID);
        bias0 = b_f0[j]; bias1 = b_f1[j]; wx = Wih_f0[j];
    } else {
        load_row(w0, Whh_b0 + j * HID);
        load_row(w1, Wih_b1 + j * HID);
        load_row(w2, Whh_b1 + j * HID);   // on hf1 (replicated bug)
        bias0 = b_b0[j]; bias1 = b_b1[j]; wx = Wih_b0[j];
    }
    const int fut = future_p[0];
    const float *xbase = x + nb0;

    for (int i = tid; i < NB * HP; i += 256) {
        ((float *)hf0s)[i] = 0.f; ((float *)hb0s)[i] = 0.f;
    }
    for (int i = tid; i < 2 * NB * HP; i += 256) {
        ((float *)hf1s)[i] = 0.f; ((float *)hb1s)[i] = 0.f;
    }
    for (int i = tid; i < NB * HID; i += 256) {
        ((float *)cf0s)[i] = 0.f; ((float *)cf1s)[i] = 0.f;
        ((float *)cb0s)[i] = 0.f; ((float *)cb1s)[i] = 0.f;
    }
    if (tid < 2 * HID) wls[tid] = Wlin[tid];
    if (tid == 0) blin_s = blin[0];

    // backward running index: rb_t = (fut - t) mod S, maintained incrementally.
    int rb = fut % S_LEN; if (rb < 0) rb += S_LEN;          // index for t=0

    if (tid < NB) {
        xs[tid] = xbase[tid];
    } else if (tid >= 128 && tid < 128 + NB) {
        xbs[tid - 128] = xbase[rb * B_TOT + (tid - 128)];
    }
    // advance rb to t=1 position for the main loop prefetcher
    rb--; if (rb < 0) rb += S_LEN;

    __syncthreads();

    const int m  = j & 31;
    const int ng = j >> 5;

    // prologue: f0_0 from zero state
    if (isF) {
#pragma unroll
        for (int n = 0; n < NB; n++) gF0[n][j] = bias0 + wx * xs[n];
    }
    __syncthreads();
    if (isF) {
        cell2(gF0[ng], cf0s[ng], hf0s[ng],
              gF0[ng + 4], cf0s[ng + 4], hf0s[ng + 4], m);
    }
    if (tid < NB) xs[tid] = xbase[B_TOT + tid];   // x_1
    __syncthreads();

    // step t computes: f0_{t+1}, f1_t, b0_t, b1_{t-1}, out_{t-2}
    for (int t = 0; t < S_LEN + 2; t++) {
        const int pb = (t + 1) & 1;   // holds hf1_{t-1}
        const int cb = t & 1;         // written with hf1_t / b1_{t-1}; holds *_{t-2} during comp
        float xreg = 0.f, xbreg = 0.f;

        // ==== compute ====
        if (isF) {
            if (t < S_LEN) {
                if (j < NB && t + 2 < S_LEN) xreg = xbase[(t + 2) * B_TOT + j];
#pragma unroll 1
                for (int n = 0; n < NB; n++) {
                    u64 a0 = 0, a1 = 0, a2 = 0, a3 = 0, a4 = 0, a5 = 0;
                    const ulonglong2 *hu = (const ulonglong2 *)hf0s[n];
                    const ulonglong2 *hv = (const ulonglong2 *)hf1s[pb][n];
#pragma unroll
                    for (int c = 0; c < 8; c++) {
                        ulonglong2 u = hu[c];
                        fma2(a0, w0[2 * c],     u.x);
                        fma2(a1, w0[2 * c + 1], u.y);
                        fma2(a2, w1[2 * c],     u.x);
                        fma2(a3, w1[2 * c + 1], u.y);
                        ulonglong2 v = hv[c];
                        fma2(a4, w2[2 * c],     v.x);
                        fma2(a5, w2[2 * c + 1], v.y);
                    }
                    add2(a0, a1);
                    gF0[n][j] = hsum2(a0) + bias0 + wx * xs[n];     // f0_{t+1}
                    add2(a2, a3); add2(a4, a5); add2(a2, a4);
                    gF1[n][j] = hsum2(a2) + bias1;                  // f1_t
                }
            }
            // out_{t-2}: reads hf1_{t-2} (buf cb) and b1_{t-2} (buf cb)
            if (t >= 2 && j >= 120) {
                int n = j - 120;
                const ulonglong2 *pf = (const ulonglong2 *)hf1s[cb][n];
                const ulonglong2 *pk = (const ulonglong2 *)hb1s[cb][n];
                const ulonglong2 *wf = (const ulonglong2 *)wls;
                u64 acc = 0, acc2 = 0;
#pragma unroll
                for (int c = 0; c < 8; c++) {
                    ulonglong2 u = pf[c], wu = wf[c];
                    fma2(acc,  wu.x, u.x);
                    fma2(acc2, wu.y, u.y);
                    ulonglong2 v = pk[c], wv = wf[c + 8];
                    fma2(acc,  wv.x, v.x);
                    fma2(acc2, wv.y, v.y);
                }
                add2(acc, acc2);
                out[(nb0 + n) * S_LEN + (t - 2)] = hsum2(acc) + blin_s;
            }
        } else {
            if (t <= S_LEN) {
                if (j < NB && t + 1 < S_LEN) xbreg = xbase[rb * B_TOT + j];
#pragma unroll 1
                for (int n = 0; n < NB; n++) {
                    u64 a0 = 0, a1 = 0, a2 = 0, a3 = 0, a4 = 0, a5 = 0;
                    const ulonglong2 *hu = (const ulonglong2 *)hb0s[n];
                    const ulonglong2 *hv = (const ulonglong2 *)hf1s[pb][n];
#pragma unroll
                    for (int c = 0; c < 8; c++) {
                        ulonglong2 u = hu[c];
                        fma2(a0, w0[2 * c],     u.x);
                        fma2(a1, w0[2 * c + 1], u.y);
                        fma2(a2, w1[2 * c],     u.x);
                        fma2(a3, w1[2 * c + 1], u.y);
                        ulonglong2 v = hv[c];
                        fma2(a4, w2[2 * c],     v.x);
                        fma2(a5, w2[2 * c + 1], v.y);
                    }
                    add2(a0, a1);
                    gB0[n][j] = hsum2(a0) + bias0 + wx * xbs[n];    // b0_t
                    add2(a2, a3); add2(a4, a5); add2(a2, a4);
                    gB1[n][j] = hsum2(a2) + bias1;                  // b1_{t-1}
                }
            }
            rb--; if (rb < 0) rb += S_LEN;
        }

        // ==== per-half barrier: gates ready within this half ====
        if (isF) asm volatile("bar.sync 1, 128;" ::: "memory");
        else     asm volatile("bar.sync 2, 128;" ::: "memory");

        // ==== finalize ====
        if (isF) {
            if (t < S_LEN) {
                cell2(gF0[ng], cf0s[ng], hf0s[ng],
                      gF0[ng + 4], cf0s[ng + 4], hf0s[ng + 4], m);            // f0_{t+1}
                cell2(gF1[ng], cf1s[ng], hf1s[cb][ng],
                      gF1[ng + 4], cf1s[ng + 4], hf1s[cb][ng + 4], m);        // f1_t -> buf cb
                if (j < NB) xs[j] = xreg;                                      // x_{t+2}
            }
        } else {
            if (t < S_LEN) {
                cell2(gB0[ng], cb0s[ng], hb0s[ng],
                      gB0[ng + 4], cb0s[ng + 4], hb0s[ng + 4], m);            // b0_t
                if (j < NB) xbs[j] = xbreg;                                    // xb_{t+1}
            }
            if (t >= 1 && t <= S_LEN) {
                // b1_{t-1} -> buffer (t-1)&1 == pb
                cell2(gB1[ng], cb1s[ng], hb1s[pb][ng],
                      gB1[ng + 4], cb1s[ng + 4], hb1s[pb][ng + 4], m);
            }
        }
        __syncthreads();   // full: publishes hf1/hb1/hf0/hb0 across halves
    }
}

extern "C" void kernel_launch(void *const *d_in, const int *in_sizes, int n_in,
                              void *d_out, int out_size)
{
    const float *x      = (const float *)d_in[0];
    const float *Wih_f0 = (const float *)d_in[1];
    const float *Whh_f0 = (const float *)d_in[2];
    const float *b_f0   = (const float *)d_in[3];
    const float *Wih_f1 = (const float *)d_in[4];
    const float *Whh_f1 = (const float *)d_in[5];
    const float *b_f1   = (const float *)d_in[6];
    const float *Wih_b0 = (const float *)d_in[7];
    const float *Whh_b0 = (const float *)d_in[8];
    const float *b_b0   = (const float *)d_in[9];
    const float *Wih_b1 = (const float *)d_in[10];
    const float *Whh_b1 = (const float *)d_in[11];
    const float *b_b1   = (const float *)d_in[12];
    const float *Wlin   = (const float *)d_in[13];
    const float *blin   = (const float *)d_in[14];
    const int   *future = (const int *)d_in[15];
    float *out = (float *)d_out;

    lstm_kernel<<<NCTA, 256>>>(x,
                               Wih_f0, Whh_f0, b_f0,
                               Wih_f1, Whh_f1, b_f1,
                               Wih_b0, Whh_b0, b_b0,
                               Wih_b1, Whh_b1, b_b1,
                               Wlin, blin, future, out);
}

// round 5
// speedup vs baseline: 3.4225x; 1.0221x over previous
#include <cuda_runtime.h>

// BidirectionalLSTMComplex: S=1024, B=2048, H=32, IN=1, OUT=1
// Round 5: balanced grid (296 CTAs x 2/SM on 148 SMs), variable NB per CTA
// (272 blocks x 7 + 24 blocks x 6 = 2048). Structure otherwise as round 4.

#define S_LEN 1024
#define B_TOT 2048
#define HID   32
#define GATES 128
#define NBMAX 7
#define NCTA  296
#define HP    36

typedef unsigned long long u64;

__device__ __forceinline__ void fma2(u64 &acc, u64 a, u64 b) {
    asm("fma.rn.f32x2 %0, %1, %2, %3;" : "=l"(acc) : "l"(a), "l"(b), "l"(acc));
}
__device__ __forceinline__ void add2(u64 &a, u64 b) {
    asm("add.rn.f32x2 %0, %1, %2;" : "=l"(a) : "l"(a), "l"(b));
}
__device__ __forceinline__ float hsum2(u64 v) {
    float lo, hi;
    asm("mov.b64 {%0,%1}, %2;" : "=f"(lo), "=f"(hi) : "l"(v));
    return lo + hi;
}
__device__ __forceinline__ float tanh_fast(float x) {
    float y;
    asm("tanh.approx.f32 %0, %1;" : "=f"(y) : "f"(x));
    return y;
}
__device__ __forceinline__ float sigm(float x) {
    return fmaf(tanh_fast(x * 0.5f), 0.5f, 0.5f);
}

__device__ __forceinline__ void load_row(u64 *w, const float *base) {
    const ulonglong2 *p = (const ulonglong2 *)base;
#pragma unroll
    for (int i = 0; i < 8; i++) {
        ulonglong2 q = p[i];
        w[2 * i]     = q.x;
        w[2 * i + 1] = q.y;
    }
}

__device__ __forceinline__ void cell1(const float *g, float *c, float *h, int m) {
    float gi = g[m], gf = g[m + 32], gg = g[m + 64], go = g[m + 96];
    float c2 = sigm(gf) * c[m] + sigm(gi) * tanh_fast(gg);
    c[m] = c2;
    h[m] = sigm(go) * tanh_fast(c2);
}

// two independent unit updates, MUFUs interleaved to pipeline
__device__ __forceinline__ void cell2(const float *g0, float *c0, float *h0,
                                      const float *g1, float *c1, float *h1, int m) {
    float ai = g0[m], af = g0[m + 32], ag = g0[m + 64], ao = g0[m + 96];
    float bi = g1[m], bf = g1[m + 32], bg = g1[m + 64], bo = g1[m + 96];
    float sfa = sigm(af), sfb = sigm(bf);
    float sia = sigm(ai), sib = sigm(bi);
    float tga = tanh_fast(ag), tgb = tanh_fast(bg);
    float soa = sigm(ao), sob = sigm(bo);
    float c2a = sfa * c0[m] + sia * tga;
    float c2b = sfb * c1[m] + sib * tgb;
    c0[m] = c2a; c1[m] = c2b;
    h0[m] = soa * tanh_fast(c2a);
    h1[m] = sob * tanh_fast(c2b);
}

__global__ void __launch_bounds__(256, 2)
lstm_kernel(const float *__restrict__ x,
            const float *__restrict__ Wih_f0, const float *__restrict__ Whh_f0, const float *__restrict__ b_f0,
            const float *__restrict__ Wih_f1, const float *__restrict__ Whh_f1, const float *__restrict__ b_f1,
            const float *__restrict__ Wih_b0, const float *__restrict__ Whh_b0, const float *__restrict__ b_b0,
            const float *__restrict__ Wih_b1, const float *__restrict__ Whh_b1, const float *__restrict__ b_b1,
            const float *__restrict__ Wlin,   const float *__restrict__ blin,
            const int *__restrict__ future_p,
            float *__restrict__ out)
{
    const int tid  = threadIdx.x;
    const int j    = tid & 127;
    const bool isF = tid < 128;

    int nb, nb0;
    if (blockIdx.x < 272) { nb = 7; nb0 = blockIdx.x * 7; }
    else                  { nb = 6; nb0 = 1904 + (blockIdx.x - 272) * 6; }

    __shared__ __align__(16) float hf0s[NBMAX][HP];
    __shared__ __align__(16) float hf1s[2][NBMAX][HP];
    __shared__ __align__(16) float hb0s[NBMAX][HP];
    __shared__ __align__(16) float hb1s[2][NBMAX][HP];
    __shared__ float cf0s[NBMAX][HID], cf1s[NBMAX][HID], cb0s[NBMAX][HID], cb1s[NBMAX][HID];
    __shared__ float gF0[NBMAX][GATES], gF1[NBMAX][GATES];
    __shared__ float gB0[NBMAX][GATES], gB1[NBMAX][GATES];
    __shared__ float xs[NBMAX], xbs[NBMAX];
    __shared__ __align__(16) float wls[2 * HID];
    __shared__ float blin_s;

    u64 w0[16], w1[16], w2[16];
    float bias0, bias1, wx;
    if (isF) {
        load_row(w0, Whh_f0 + j * HID);
        load_row(w1, Wih_f1 + j * HID);
        load_row(w2, Whh_f1 + j * HID);
        bias0 = b_f0[j]; bias1 = b_f1[j]; wx = Wih_f0[j];
    } else {
        load_row(w0, Whh_b0 + j * HID);
        load_row(w1, Wih_b1 + j * HID);
        load_row(w2, Whh_b1 + j * HID);   // on hf1 (replicated bug)
        bias0 = b_b0[j]; bias1 = b_b1[j]; wx = Wih_b0[j];
    }
    const int fut = future_p[0];
    const float *xbase = x + nb0;

    for (int i = tid; i < NBMAX * HP; i += 256) {
        ((float *)hf0s)[i] = 0.f; ((float *)hb0s)[i] = 0.f;
    }
    for (int i = tid; i < 2 * NBMAX * HP; i += 256) {
        ((float *)hf1s)[i] = 0.f; ((float *)hb1s)[i] = 0.f;
    }
    for (int i = tid; i < NBMAX * HID; i += 256) {
        ((float *)cf0s)[i] = 0.f; ((float *)cf1s)[i] = 0.f;
        ((float *)cb0s)[i] = 0.f; ((float *)cb1s)[i] = 0.f;
    }
    if (tid < 2 * HID) wls[tid] = Wlin[tid];
    if (tid == 0) blin_s = blin[0];

    int rb = fut % S_LEN; if (rb < 0) rb += S_LEN;     // backward index for t=0

    if (tid < nb) {
        xs[tid] = xbase[tid];
    } else if (tid >= 128 && tid < 128 + nb) {
        xbs[tid - 128] = xbase[rb * B_TOT + (tid - 128)];
    }
    rb--; if (rb < 0) rb += S_LEN;                     // index for t=1

    __syncthreads();

    const int m  = j & 31;
    const int ng = j >> 5;
    const bool two = (ng + 4 < nb);    // block-uniform per warp

    // prologue: f0_0 from zero state
    if (isF) {
        for (int n = 0; n < nb; n++) gF0[n][j] = bias0 + wx * xs[n];
    }
    __syncthreads();
    if (isF) {
        if (two) cell2(gF0[ng], cf0s[ng], hf0s[ng],
                       gF0[ng + 4], cf0s[ng + 4], hf0s[ng + 4], m);
        else     cell1(gF0[ng], cf0s[ng], hf0s[ng], m);
    }
    if (tid < nb) xs[tid] = xbase[B_TOT + tid];   // x_1
    __syncthreads();

    // step t computes: f0_{t+1}, f1_t, b0_t, b1_{t-1}, out_{t-2}
    for (int t = 0; t < S_LEN + 2; t++) {
        const int pb = (t + 1) & 1;
        const int cb = t & 1;
        float xreg = 0.f, xbreg = 0.f;

        // ==== compute ====
        if (isF) {
            if (t < S_LEN) {
                if (j < nb && t + 2 < S_LEN) xreg = xbase[(t + 2) * B_TOT + j];
#pragma unroll 1
                for (int n = 0; n < nb; n++) {
                    u64 a0 = 0, a1 = 0, a2 = 0, a3 = 0, a4 = 0, a5 = 0;
                    const ulonglong2 *hu = (const ulonglong2 *)hf0s[n];
                    const ulonglong2 *hv = (const ulonglong2 *)hf1s[pb][n];
#pragma unroll
                    for (int c = 0; c < 8; c++) {
                        ulonglong2 u = hu[c];
                        fma2(a0, w0[2 * c],     u.x);
                        fma2(a1, w0[2 * c + 1], u.y);
                        fma2(a2, w1[2 * c],     u.x);
                        fma2(a3, w1[2 * c + 1], u.y);
                        ulonglong2 v = hv[c];
                        fma2(a4, w2[2 * c],     v.x);
                        fma2(a5, w2[2 * c + 1], v.y);
                    }
                    add2(a0, a1);
                    gF0[n][j] = hsum2(a0) + bias0 + wx * xs[n];     // f0_{t+1}
                    add2(a2, a3); add2(a4, a5); add2(a2, a4);
                    gF1[n][j] = hsum2(a2) + bias1;                  // f1_t
                }
            }
            // out_{t-2}: reads hf1_{t-2} (buf cb) and hb1_{t-2} (buf cb)
            if (t >= 2 && j >= 120) {
                int n = j - 120;
                if (n < nb) {
                    const ulonglong2 *pf = (const ulonglong2 *)hf1s[cb][n];
                    const ulonglong2 *pk = (const ulonglong2 *)hb1s[cb][n];
                    const ulonglong2 *wf = (const ulonglong2 *)wls;
                    u64 acc = 0, acc2 = 0;
#pragma unroll
                    for (int c = 0; c < 8; c++) {
                        ulonglong2 u = pf[c], wu = wf[c];
                        fma2(acc,  wu.x, u.x);
                        fma2(acc2, wu.y, u.y);
                        ulonglong2 v = pk[c], wv = wf[c + 8];
                        fma2(acc,  wv.x, v.x);
                        fma2(acc2, wv.y, v.y);
                    }
                    add2(acc, acc2);
                    out[(nb0 + n) * S_LEN + (t - 2)] = hsum2(acc) + blin_s;
                }
            }
        } else {
            if (t <= S_LEN) {
                if (j < nb && t + 1 < S_LEN) xbreg = xbase[rb * B_TOT + j];
#pragma unroll 1
                for (int n = 0; n < nb; n++) {
                    u64 a0 = 0, a1 = 0, a2 = 0, a3 = 0, a4 = 0, a5 = 0;
                    const ulonglong2 *hu = (const ulonglong2 *)hb0s[n];
                    const ulonglong2 *hv = (const ulonglong2 *)hf1s[pb][n];
#pragma unroll
                    for (int c = 0; c < 8; c++) {
                        ulonglong2 u = hu[c];
                        fma2(a0, w0[2 * c],     u.x);
                        fma2(a1, w0[2 * c + 1], u.y);
                        fma2(a2, w1[2 * c],     u.x);
                        fma2(a3, w1[2 * c + 1], u.y);
                        ulonglong2 v = hv[c];
                        fma2(a4, w2[2 * c],     v.x);
                        fma2(a5, w2[2 * c + 1], v.y);
                    }
                    add2(a0, a1);
                    gB0[n][j] = hsum2(a0) + bias0 + wx * xbs[n];    // b0_t
                    add2(a2, a3); add2(a4, a5); add2(a2, a4);
                    gB1[n][j] = hsum2(a2) + bias1;                  // b1_{t-1}
                }
            }
            rb--; if (rb < 0) rb += S_LEN;
        }

        // per-half barrier: gates ready within this half
        if (isF) asm volatile("bar.sync 1, 128;" ::: "memory");
        else     asm volatile("bar.sync 2, 128;" ::: "memory");

        // ==== finalize ====
        if (isF) {
            if (t < S_LEN) {
                if (two) {
                    cell2(gF0[ng], cf0s[ng], hf0s[ng],
                          gF0[ng + 4], cf0s[ng + 4], hf0s[ng + 4], m);         // f0_{t+1}
                    cell2(gF1[ng], cf1s[ng], hf1s[cb][ng],
                          gF1[ng + 4], cf1s[ng + 4], hf1s[cb][ng + 4], m);     // f1_t
                } else {
                    cell2(gF0[ng], cf0s[ng], hf0s[ng],
                          gF1[ng], cf1s[ng], hf1s[cb][ng], m);                 // interleave f0+f1
                }
                if (j < nb) xs[j] = xreg;                                      // x_{t+2}
            }
        } else {
            if (t < S_LEN) {
                if (two) cell2(gB0[ng], cb0s[ng], hb0s[ng],
                               gB0[ng + 4], cb0s[ng + 4], hb0s[ng + 4], m);    // b0_t
                else     cell1(gB0[ng], cb0s[ng], hb0s[ng], m);
                if (j < nb) xbs[j] = xbreg;                                    // xb_{t+1}
            }
            if (t >= 1 && t <= S_LEN) {
                if (two) cell2(gB1[ng], cb1s[ng], hb1s[pb][ng],
                               gB1[ng + 4], cb1s[ng + 4], hb1s[pb][ng + 4], m); // b1_{t-1}
                else     cell1(gB1[ng], cb1s[ng], hb1s[pb][ng], m);
            }
        }
        __syncthreads();
    }
}

extern "C" void kernel_launch(void *const *d_in, const int *in_sizes, int n_in,
                              void *d_out, int out_size)
{
    const float *x      = (const float *)d_in[0];
    const float *Wih_f0 = (const float *)d_in[1];
    const float *Whh_f0 = (const float *)d_in[2];
    const float *b_f0   = (const float *)d_in[3];
    const float *Wih_f1 = (const float *)d_in[4];
    const float *Whh_f1 = (const float *)d_in[5];
    const float *b_f1   = (const float *)d_in[6];
    const float *Wih_b0 = (const float *)d_in[7];
    const float *Whh_b0 = (const float *)d_in[8];
    const float *b_b0   = (const float *)d_in[9];
    const float *Wih_b1 = (const float *)d_in[10];
    const float *Whh_b1 = (const float *)d_in[11];
    const float *b_b1   = (const float *)d_in[12];
    const float *Wlin   = (const float *)d_in[13];
    const float *blin   = (const float *)d_in[14];
    const int   *future = (const int *)d_in[15];
    float *out = (float *)d_out;

    lstm_kernel<<<NCTA, 256>>>(x,
                               Wih_f0, Whh_f0, b_f0,
                               Wih_f1, Whh_f1, b_f1,
                               Wih_b0, Whh_b0, b_b0,
                               Wih_b1, Whh_b1, b_b1,
                               Wlin, blin, future, out);
}

// round 6
// speedup vs baseline: 3.5549x; 1.0387x over previous
#include <cuda_runtime.h>

// BidirectionalLSTMComplex: S=1024, B=2048, H=32, IN=1, OUT=1
// Round 6: uniform compile-time NB=7 on 296 CTAs (2072 slots, 24 dead lanes
// masked via guarded loads/stores). Constant loop bounds restore folded
// addressing (alu 11.6% -> ~6%). Structure otherwise as round 5.

#define S_LEN 1024
#define B_TOT 2048
#define HID   32
#define GATES 128
#define NB    7
#define NCTA  296
#define HP    36

typedef unsigned long long u64;

__device__ __forceinline__ void fma2(u64 &acc, u64 a, u64 b) {
    asm("fma.rn.f32x2 %0, %1, %2, %3;" : "=l"(acc) : "l"(a), "l"(b), "l"(acc));
}
__device__ __forceinline__ void add2(u64 &a, u64 b) {
    asm("add.rn.f32x2 %0, %1, %2;" : "=l"(a) : "l"(a), "l"(b));
}
__device__ __forceinline__ float hsum2(u64 v) {
    float lo, hi;
    asm("mov.b64 {%0,%1}, %2;" : "=f"(lo), "=f"(hi) : "l"(v));
    return lo + hi;
}
__device__ __forceinline__ float tanh_fast(float x) {
    float y;
    asm("tanh.approx.f32 %0, %1;" : "=f"(y) : "f"(x));
    return y;
}
__device__ __forceinline__ float sigm(float x) {
    return fmaf(tanh_fast(x * 0.5f), 0.5f, 0.5f);
}

__device__ __forceinline__ void load_row(u64 *w, const float *base) {
    const ulonglong2 *p = (const ulonglong2 *)base;
#pragma unroll
    for (int i = 0; i < 8; i++) {
        ulonglong2 q = p[i];
        w[2 * i]     = q.x;
        w[2 * i + 1] = q.y;
    }
}

__device__ __forceinline__ void cell1(const float *g, float *c, float *h, int m) {
    float gi = g[m], gf = g[m + 32], gg = g[m + 64], go = g[m + 96];
    float c2 = sigm(gf) * c[m] + sigm(gi) * tanh_fast(gg);
    c[m] = c2;
    h[m] = sigm(go) * tanh_fast(c2);
}

// two independent unit updates, MUFUs interleaved to pipeline
__device__ __forceinline__ void cell2(const float *g0, float *c0, float *h0,
                                      const float *g1, float *c1, float *h1, int m) {
    float ai = g0[m], af = g0[m + 32], ag = g0[m + 64], ao = g0[m + 96];
    float bi = g1[m], bf = g1[m + 32], bg = g1[m + 64], bo = g1[m + 96];
    float sfa = sigm(af), sfb = sigm(bf);
    float sia = sigm(ai), sib = sigm(bi);
    float tga = tanh_fast(ag), tgb = tanh_fast(bg);
    float soa = sigm(ao), sob = sigm(bo);
    float c2a = sfa * c0[m] + sia * tga;
    float c2b = sfb * c1[m] + sib * tgb;
    c0[m] = c2a; c1[m] = c2b;
    h0[m] = soa * tanh_fast(c2a);
    h1[m] = sob * tanh_fast(c2b);
}

__global__ void __launch_bounds__(256, 2)
lstm_kernel(const float *__restrict__ x,
            const float *__restrict__ Wih_f0, const float *__restrict__ Whh_f0, const float *__restrict__ b_f0,
            const float *__restrict__ Wih_f1, const float *__restrict__ Whh_f1, const float *__restrict__ b_f1,
            const float *__restrict__ Wih_b0, const float *__restrict__ Whh_b0, const float *__restrict__ b_b0,
            const float *__restrict__ Wih_b1, const float *__restrict__ Whh_b1, const float *__restrict__ b_b1,
            const float *__restrict__ Wlin,   const float *__restrict__ blin,
            const int *__restrict__ future_p,
            float *__restrict__ out)
{
    const int tid  = threadIdx.x;
    const int j    = tid & 127;
    const bool isF = tid < 128;
    const int nb0  = blockIdx.x * NB;        // may exceed B_TOT-7 on tail blocks

    __shared__ __align__(16) float hf0s[NB][HP];
    __shared__ __align__(16) float hf1s[2][NB][HP];
    __shared__ __align__(16) float hb0s[NB][HP];
    __shared__ __align__(16) float hb1s[2][NB][HP];
    __shared__ float cf0s[NB][HID], cf1s[NB][HID], cb0s[NB][HID], cb1s[NB][HID];
    __shared__ float gF0[NB][GATES], gF1[NB][GATES];
    __shared__ float gB0[NB][GATES], gB1[NB][GATES];
    __shared__ float xs[NB], xbs[NB];
    __shared__ __align__(16) float wls[2 * HID];
    __shared__ float blin_s;

    u64 w0[16], w1[16], w2[16];
    float bias0, bias1, wx;
    if (isF) {
        load_row(w0, Whh_f0 + j * HID);
        load_row(w1, Wih_f1 + j * HID);
        load_row(w2, Whh_f1 + j * HID);
        bias0 = b_f0[j]; bias1 = b_f1[j]; wx = Wih_f0[j];
    } else {
        load_row(w0, Whh_b0 + j * HID);
        load_row(w1, Wih_b1 + j * HID);
        load_row(w2, Whh_b1 + j * HID);   // on hf1 (replicated bug)
        bias0 = b_b0[j]; bias1 = b_b1[j]; wx = Wih_b0[j];
    }
    const int fut = future_p[0];
    const float *xbase = x + nb0;
    // validity of batch lane (j < NB context): dead lanes read 0, never store
    const bool jval = (j < NB) && (nb0 + j < B_TOT);

    for (int i = tid; i < NB * HP; i += 256) {
        ((float *)hf0s)[i] = 0.f; ((float *)hb0s)[i] = 0.f;
    }
    for (int i = tid; i < 2 * NB * HP; i += 256) {
        ((float *)hf1s)[i] = 0.f; ((float *)hb1s)[i] = 0.f;
    }
    for (int i = tid; i < NB * HID; i += 256) {
        ((float *)cf0s)[i] = 0.f; ((float *)cf1s)[i] = 0.f;
        ((float *)cb0s)[i] = 0.f; ((float *)cb1s)[i] = 0.f;
    }
    if (tid < 2 * HID) wls[tid] = Wlin[tid];
    if (tid == 0) blin_s = blin[0];

    int rb = fut % S_LEN; if (rb < 0) rb += S_LEN;     // backward index for t=0

    if (tid < NB) {
        xs[tid] = jval ? xbase[tid] : 0.f;
    } else if (tid >= 128 && tid < 128 + NB) {
        xbs[tid - 128] = jval ? xbase[rb * B_TOT + (tid - 128)] : 0.f;
    }
    rb--; if (rb < 0) rb += S_LEN;                     // index for t=1

    __syncthreads();

    const int m  = j & 31;
    const int ng = j >> 5;

    // prologue: f0_0 from zero state
    if (isF) {
#pragma unroll
        for (int n = 0; n < NB; n++) gF0[n][j] = bias0 + wx * xs[n];
    }
    __syncthreads();
    if (isF) {
        if (ng < 3) cell2(gF0[ng], cf0s[ng], hf0s[ng],
                          gF0[ng + 4], cf0s[ng + 4], hf0s[ng + 4], m);
        else        cell1(gF0[3], cf0s[3], hf0s[3], m);
    }
    if (tid < NB) xs[tid] = jval ? xbase[B_TOT + tid] : 0.f;   // x_1
    __syncthreads();

    // step t computes: f0_{t+1}, f1_t, b0_t, b1_{t-1}, out_{t-2}
    for (int t = 0; t < S_LEN + 2; t++) {
        const int pb = (t + 1) & 1;
        const int cb = t & 1;
        float xreg = 0.f, xbreg = 0.f;

        // ==== compute ====
        if (isF) {
            if (t < S_LEN) {
                if (jval && t + 2 < S_LEN) xreg = xbase[(t + 2) * B_TOT + j];
#pragma unroll 1
                for (int n = 0; n < NB; n++) {
                    u64 a0 = 0, a1 = 0, a2 = 0, a3 = 0, a4 = 0, a5 = 0;
                    const ulonglong2 *hu = (const ulonglong2 *)hf0s[n];
                    const ulonglong2 *hv = (const ulonglong2 *)hf1s[pb][n];
#pragma unroll
                    for (int c = 0; c < 8; c++) {
                        ulonglong2 u = hu[c];
                        fma2(a0, w0[2 * c],     u.x);
                        fma2(a1, w0[2 * c + 1], u.y);
                        fma2(a2, w1[2 * c],     u.x);
                        fma2(a3, w1[2 * c + 1], u.y);
                        ulonglong2 v = hv[c];
                        fma2(a4, w2[2 * c],     v.x);
                        fma2(a5, w2[2 * c + 1], v.y);
                    }
                    add2(a0, a1);
                    gF0[n][j] = hsum2(a0) + bias0 + wx * xs[n];     // f0_{t+1}
                    add2(a2, a3); add2(a4, a5); add2(a2, a4);
                    gF1[n][j] = hsum2(a2) + bias1;                  // f1_t
                }
            }
            // out_{t-2}: reads hf1_{t-2} (buf cb) and hb1_{t-2} (buf cb)
            if (t >= 2 && j >= 120) {
                int n = j - 120;
                if (n < NB && nb0 + n < B_TOT) {
                    const ulonglong2 *pf = (const ulonglong2 *)hf1s[cb][n];
                    const ulonglong2 *pk = (const ulonglong2 *)hb1s[cb][n];
                    const ulonglong2 *wf = (const ulonglong2 *)wls;
                    u64 acc = 0, acc2 = 0;
#pragma unroll
                    for (int c = 0; c < 8; c++) {
                        ulonglong2 u = pf[c], wu = wf[c];
                        fma2(acc,  wu.x, u.x);
                        fma2(acc2, wu.y, u.y);
                        ulonglong2 v = pk[c], wv = wf[c + 8];
                        fma2(acc,  wv.x, v.x);
                        fma2(acc2, wv.y, v.y);
                    }
                    add2(acc, acc2);
                    out[(nb0 + n) * S_LEN + (t - 2)] = hsum2(acc) + blin_s;
                }
            }
        } else {
            if (t <= S_LEN) {
                if (jval && t + 1 < S_LEN) xbreg = xbase[rb * B_TOT + j];
#pragma unroll 1
                for (int n = 0; n < NB; n++) {
                    u64 a0 = 0, a1 = 0, a2 = 0, a3 = 0, a4 = 0, a5 = 0;
                    const ulonglong2 *hu = (const ulonglong2 *)hb0s[n];
                    const ulonglong2 *hv = (const ulonglong2 *)hf1s[pb][n];
#pragma unroll
                    for (int c = 0; c < 8; c++) {
                        ulonglong2 u = hu[c];
                        fma2(a0, w0[2 * c],     u.x);
                        fma2(a1, w0[2 * c + 1], u.y);
                        fma2(a2, w1[2 * c],     u.x);
                        fma2(a3, w1[2 * c + 1], u.y);
                        ulonglong2 v = hv[c];
                        fma2(a4, w2[2 * c],     v.x);
                        fma2(a5, w2[2 * c + 1], v.y);
                    }
                    add2(a0, a1);
                    gB0[n][j] = hsum2(a0) + bias0 + wx * xbs[n];    // b0_t
                    add2(a2, a3); add2(a4, a5); add2(a2, a4);
                    gB1[n][j] = hsum2(a2) + bias1;                  // b1_{t-1}
                }
            }
            rb--; if (rb < 0) rb += S_LEN;
        }

        // per-half barrier: gates ready within this half
        if (isF) asm volatile("bar.sync 1, 128;" ::: "memory");
        else     asm volatile("bar.sync 2, 128;" ::: "memory");

        // ==== finalize ====
        if (isF) {
            if (t < S_LEN) {
                if (ng < 3) {
                    cell2(gF0[ng], cf0s[ng], hf0s[ng],
                          gF0[ng + 4], cf0s[ng + 4], hf0s[ng + 4], m);         // f0_{t+1}
                    cell2(gF1[ng], cf1s[ng], hf1s[cb][ng],
                          gF1[ng + 4], cf1s[ng + 4], hf1s[cb][ng + 4], m);     // f1_t
                } else {
                    cell2(gF0[3], cf0s[3], hf0s[3],
                          gF1[3], cf1s[3], hf1s[cb][3], m);                    // n=3: f0+f1
                }
                if (j < NB) xs[j] = xreg;                                      // x_{t+2}
            }
        } else {
            if (t < S_LEN) {
                if (ng < 3) cell2(gB0[ng], cb0s[ng], hb0s[ng],
                                  gB0[ng + 4], cb0s[ng + 4], hb0s[ng + 4], m); // b0_t
                else        cell1(gB0[3], cb0s[3], hb0s[3], m);
                if (j < NB) xbs[j] = xbreg;                                    // xb_{t+1}
            }
            if (t >= 1 && t <= S_LEN) {
                if (ng < 3) cell2(gB1[ng], cb1s[ng], hb1s[pb][ng],
                                  gB1[ng + 4], cb1s[ng + 4], hb1s[pb][ng + 4], m); // b1_{t-1}
                else        cell1(gB1[3], cb1s[3], hb1s[pb][3], m);
            }
        }
        __syncthreads();
    }
}

extern "C" void kernel_launch(void *const *d_in, const int *in_sizes, int n_in,
                              void *d_out, int out_size)
{
    const float *x      = (const float *)d_in[0];
    const float *Wih_f0 = (const float *)d_in[1];
    const float *Whh_f0 = (const float *)d_in[2];
    const float *b_f0   = (const float *)d_in[3];
    const float *Wih_f1 = (const float *)d_in[4];
    const float *Whh_f1 = (const float *)d_in[5];
    const float *b_f1   = (const float *)d_in[6];
    const float *Wih_b0 = (const float *)d_in[7];
    const float *Whh_b0 = (const float *)d_in[8];
    const float *b_b0   = (const float *)d_in[9];
    const float *Wih_b1 = (const float *)d_in[10];
    const float *Whh_b1 = (const float *)d_in[11];
    const float *b_b1   = (const float *)d_in[12];
    const float *Wlin   = (const float *)d_in[13];
    const float *blin   = (const float *)d_in[14];
    const int   *future = (const int *)d_in[15];
    float *out = (float *)d_out;

    lstm_kernel<<<NCTA, 256>>>(x,
                               Wih_f0, Whh_f0, b_f0,
                               Wih_f1, Whh_f1, b_f1,
                               Wih_b0, Whh_b0, b_b0,
                               Wih_b1, Whh_b1, b_b1,
                               Wlin, blin, future, out);
}